// round 17
// baseline (speedup 1.0000x reference)
#include <cuda_runtime.h>

#define IMG    1024
#define OUTD   1016
#define TILE_W 120             // output cols per CTA (input span 128 = 32 lanes x 4)
#define TILE_H 42
#define IN_H   (TILE_H + 8)    // 50 input rows
#define HS     128             // smem row stride (floats); h[0..123] valid
#define NT     320
#define NW     (NT / 32)       // 10 warps
#define STRIPH 21              // output rows per strip
#define NSTEP  (STRIPH + 4)    // 25 D-rows per strip (21 outputs + 4 warmup)

__device__ __forceinline__ float4 ld4g(const float* __restrict__ img, int gr, int gc) {
    float4 v = make_float4(0.f, 0.f, 0.f, 0.f);
    if (gr < IMG) {
        const float* row = img + (size_t)gr * IMG;
        if (gc + 3 < IMG) {
            v = *(const float4*)(row + gc);
        } else {
            if (gc     < IMG) v.x = row[gc];
            if (gc + 1 < IMG) v.y = row[gc + 1];
            if (gc + 2 < IMG) v.z = row[gc + 2];
        }
    }
    return v;
}

// Horizontal 5-sum of one 128-col input row (cols gc0..gc0+127) into hrow[0..127].
// Lane ln computes h[4ln..4ln+3]; h[0..123] are meaningful (lane 31's tail uses
// shuffle garbage but stays in-bounds and is never read). 4 shuffles, no halo.
__device__ __forceinline__ void hrow_sum(const float* __restrict__ img, int gr,
                                         int gc0, float* hrow, int ln) {
    const unsigned m = 0xFFFFFFFFu;
    float4 v = ld4g(img, gr, gc0 + 4 * ln);
    float4 nb;
    nb.x = __shfl_down_sync(m, v.x, 1);
    nb.y = __shfl_down_sync(m, v.y, 1);
    nb.z = __shfl_down_sync(m, v.z, 1);
    nb.w = __shfl_down_sync(m, v.w, 1);
    float h0 = (v.x + v.y) + (v.z + v.w) + nb.x;
    float h1 = h0 - v.x + nb.y;
    float h2 = h1 - v.y + nb.z;
    float h3 = h2 - v.z + nb.w;
    *(float4*)(hrow + 4 * ln) = make_float4(h0, h1, h2, h3);
}

__global__ __launch_bounds__(NT, 4) void cov_kernel(
    const float* __restrict__ x, const float* __restrict__ y,
    float* __restrict__ out)
{
    extern __shared__ float sm[];
    float* hA = sm;              // [IN_H][HS] : horizontal 5-sums of x (read-only after P1)
    float* hB = sm + IN_H * HS;  // [IN_H][HS] : horizontal 5-sums of y

    const int bx  = blockIdx.x * TILE_W;
    const int by  = blockIdx.y * TILE_H;
    const int n   = blockIdx.z;
    const int tid = threadIdx.x;
    const int wid = tid >> 5;
    const int ln  = tid & 31;

    const size_t ibase = (size_t)n * IMG * IMG;
    const float* xp = x + ibase;
    const float* yp = y + ibase;

    // ---- Phase 1: global load + horizontal 5-sums for x and y (halo-free) ----
    for (int r = wid; r < IN_H; r += NW) {
        const int gr = by + r;
        hrow_sum(xp, gr, bx, hA + r * HS, ln);
        hrow_sum(yp, gr, bx, hB + r * HS, ln);
    }
    __syncthreads();   // the only barrier: hA/hB are read-only from here on

    // ---- Phase 2 (fused): vertical 5-sums, deviation product, horizontal 5-sum
    // of D via 4 PARALLEL warp shuffles (one shfl level on the critical path),
    // vertical 5-sum of that via register ring, direct global store.
    // Center loads are UNCONDITIONAL with clamped addresses: out-of-range
    // lanes/rows read garbage that provably reaches only masked outputs
    // (col garbage: last tile q>=62 -> outputs qr>=58 > 55 masked; row garbage:
    // D rows >= 1022 -> oy >= 1018 masked by klim), and clamped addresses stay
    // inside the image. Unpredicated loads let ptxas batch/hoist them (MLP).
    {
        const unsigned FULL = 0xFFFFFFFFu;
        const int strip = wid / 5;               // 0..1
        const int wseg  = wid % 5;
        const int p0    = strip * STRIPH;        // 0 or 21
        const int qr    = wseg * 28 + ln;        // nominal D column (0..139)
        const int q     = qr < 123 ? qr : 123;   // clamp for safe smem reads

        const float* cA = hA + q;
        const float* cB = hB + q;
        float rgA[5], rgB[5], rd[5];
        #pragma unroll
        for (int t = 0; t < 5; ++t) {
            rgA[t] = cA[(p0 + t) * HS];
            rgB[t] = cB[(p0 + t) * HS];
            rd[t]  = 0.f;
        }
        float sA = ((rgA[0] + rgA[1]) + (rgA[2] + rgA[3])) + rgA[4];
        float sB = ((rgB[0] + rgB[1]) + (rgB[2] + rgB[3])) + rgB[4];
        float vd = 0.f;

        const int gc     = min(bx + q + 2, IMG - 1);     // clamped center column
        const int rowlim = IMG - (by + p0 + 2);          // #valid center rows
        const float* xc = xp + (size_t)(by + p0 + 2) * IMG + gc;
        const float* yc = yp + (size_t)(by + p0 + 2) * IMG + gc;

        // output col = qr (lanes 0..27 only); output row oy = by + p0 + k - 4
        const bool jout = (ln < 28) && (qr < TILE_W) && (bx + qr < OUTD);
        const int  klim = min(NSTEP, OUTD - by - p0 + 4);   // oy < OUTD
        float* ob = out + (size_t)n * OUTD * OUTD + bx + qr;

        #pragma unroll
        for (int k = 0; k < NSTEP; ++k) {
            const int kc = min(k, rowlim - 1);           // clamped row offset
            float xv = xc[(size_t)kc * IMG];             // unconditional L2-hit load
            float yv = yc[(size_t)kc * IMG];
            float d  = (xv - sA * 0.04f) * (yv - sB * 0.04f);

            // horizontal 5-sum of D: 4 parallel shuffles, one level of latency
            float s1 = __shfl_down_sync(FULL, d, 1);
            float s2 = __shfl_down_sync(FULL, d, 2);
            float s3 = __shfl_down_sync(FULL, d, 3);
            float s4 = __shfl_down_sync(FULL, d, 4);
            float hd = ((d + s1) + (s2 + s3)) + s4;

            vd += hd - rd[k % 5];
            rd[k % 5] = hd;

            if (k >= 4 && k < klim && jout)
                ob[(size_t)(by + p0 + k - 4) * OUTD] = vd * 0.04f;

            if (k < NSTEP - 1) {
                float nwA = cA[(p0 + k + 5) * HS];
                sA += nwA - rgA[k % 5];  rgA[k % 5] = nwA;
                float nwB = cB[(p0 + k + 5) * HS];
                sB += nwB - rgB[k % 5];  rgB[k % 5] = nwB;
            }
        }
    }
}

extern "C" void kernel_launch(void* const* d_in, const int* in_sizes, int n_in,
                              void* d_out, int out_size) {
    const float* x = (const float*)d_in[0];
    const float* y = (const float*)d_in[1];
    // d_in[2] = mean_mask (uniform 1/25, folded into the 0.04f constants)
    float* out = (float*)d_out;

    const int smem = 2 * IN_H * HS * (int)sizeof(float);   // 51200 B
    cudaFuncSetAttribute(cov_kernel, cudaFuncAttributeMaxDynamicSharedMemorySize, smem);

    dim3 grid((OUTD + TILE_W - 1) / TILE_W,    // 9
              (OUTD + TILE_H - 1) / TILE_H,    // 25
              16);
    cov_kernel<<<grid, NT, smem>>>(x, y, out);
}